// round 13
// baseline (speedup 1.0000x reference)
#include <cuda_runtime.h>
#include <cuda_bf16.h>

// MultiTaskLoss: B=64 samples, 512x512, scalar loss output.
// R13: back to two kernels (fusion was neutral). Pointwise math switched to
//      direct sigmoid: e=exp(-x), p=rcp(1+e), sp_neg=-log(p), sp_pos=x+sp_neg.
//      No fabs / no p-select / 1-op softplus. One sp consumed per pixel;
//      Sbg derived as Sall-Sfg in finalize.

#define BN 64
#define HH 512
#define WW 512
#define NPIX (HH * WW)
#define MAIN_GRID (BN * NPIX / 16 / 256)
#define PROWS (HH + 20)      // 10 pad rows top/bottom

__device__ unsigned long long g_dxh[BN * PROWS * WW / 8];   // horiz d^2, u8x8
__device__ float              g_acc[BN * 8];
__device__ unsigned           g_done;

// ---------------------------------------------------------------------------
// nearest-set-bit distance^2 (clamped 101) from center (bit 10) of 21-bit window
__device__ __forceinline__ int win_d2(unsigned win) {
    unsigned lo = win & 0x7FFu;            // bits 0..10 (left side, center incl)
    unsigned hi = win >> 10;               // bits 0..10 (right side, center incl)
    int dl = __clz(lo) - 21;               // lo==0 -> 11 (no guard needed)
    int dh = __clz(__brev(hi));            // lowest set bit idx; hi==0 -> 32
    int d  = min(min(dl, dh), 11);
    return min(d * d, 101);
}

// ---------------------------------------------------------------------------
// Fused: build 8 row-masks in smem via ballots, then emit horizontal d^2 (u8).
// grid (65, 64): blockIdx.x==64 handles pad rows + accumulator init.
__global__ void __launch_bounds__(512) maskdxh_kernel(const float4* __restrict__ targets4) {
    int b = blockIdx.y;
    int t = threadIdx.x;

    if (blockIdx.x == 64) {
        for (int i = t; i < 20 * 64; i += 512) {
            int r = i >> 6;
            int row = (r < 10) ? r : r + 512;   // 0..9 and 522..531
            g_dxh[(b * PROWS + row) * 64 + (i & 63)] = 0x6565656565656565ull;
        }
        if (b == 0) {
            if (t < BN * 8) g_acc[t] = 0.0f;
            if (t == 0)     g_done = 0u;
        }
        return;
    }

    __shared__ unsigned smask[8][18];   // 8 rows, 16 words + 1 pad each side

    int y0 = blockIdx.x * 8;            // first of 8 rows this block owns

    if (t < 144) ((unsigned*)smask)[t] = 0u;
    __syncthreads();

    // --- build masks: 8 px/thread, 4-lane REDUX.OR -> one word / 32 px ---
    int g4 = ((b * NPIX + y0 * WW) >> 2) + t * 2;   // float4 index
    float4 v0 = targets4[g4 + 0];
    float4 v1 = targets4[g4 + 1];
    unsigned m =
          (v0.x > 0.5f ? 0x01u : 0u) | (v0.y > 0.5f ? 0x02u : 0u)
        | (v0.z > 0.5f ? 0x04u : 0u) | (v0.w > 0.5f ? 0x08u : 0u)
        | (v1.x > 0.5f ? 0x10u : 0u) | (v1.y > 0.5f ? 0x20u : 0u)
        | (v1.z > 0.5f ? 0x40u : 0u) | (v1.w > 0.5f ? 0x80u : 0u);

    unsigned lane  = t & 31;
    unsigned gmask = 0xFu << (lane & ~3u);          // 4-lane group = 32 px
    unsigned word  = __reduce_or_sync(gmask, m << ((lane & 3) * 8));
    if ((lane & 3) == 0) {
        int p0 = t * 8;
        smask[p0 >> 9][1 + ((p0 & 511) >> 5)] = word;
    }
    __syncthreads();

    // --- horizontal d^2, 8 px/thread (one u64 output) ---
    int r  = t >> 6;                    // row within strip
    int x0 = (t & 63) << 3;             // first pixel in row
    int s  = x0 - 10;
    const unsigned* rp = &smask[r][0] + 1 + (s >> 5);
    unsigned long long w =
        (((unsigned long long)rp[1] << 32) | rp[0]) >> (s & 31);
    unsigned long long out = 0ull;
    #pragma unroll
    for (int j = 0; j < 8; ++j) {
        unsigned win = (unsigned)(w >> j) & 0x1FFFFFu;
        out |= (unsigned long long)win_d2(win) << (8 * j);
    }
    g_dxh[(unsigned long long)(b * PROWS + 10 + y0 + r) * 64 + (x0 >> 3)] = out;
}

// ---------------------------------------------------------------------------
__global__ void __launch_bounds__(256, 6) main_kernel(
    const float4* __restrict__ preds4,
    const int*    __restrict__ task_ids,
    float*        __restrict__ out)
{
    __shared__ float sTab[102];
    if (threadIdx.x < 102) sTab[threadIdx.x] = fminf(sqrtf((float)threadIdx.x), 10.0f);

    int q = blockIdx.x * blockDim.x + threadIdx.x;   // 16-px strip index
    int b  = q >> 14;                                // 16384 strips per sample
    int y  = (q >> 5) & 511;
    int xo = q & 31;                                 // 16-px group in row

    float4 xv[4];
    #pragma unroll
    for (int k = 0; k < 4; ++k) xv[k] = preds4[q * 4 + k];

    // ---- byte-SIMD vertical DT (128-bit loads) ----
    const ulonglong2* bp = (const ulonglong2*)g_dxh + (b * PROWS + 10 + y) * 32 + xo;
    ulonglong2 cur = *bp;
    unsigned bw[4] = {(unsigned)cur.x, (unsigned)(cur.x >> 32),
                      (unsigned)cur.y, (unsigned)(cur.y >> 32)};

    #pragma unroll 1
    for (int ady = 1; ady <= 10; ++ady) {
        int a2 = ady * ady;
        unsigned m4 = __vmaxu4(__vmaxu4(bw[0], bw[1]), __vmaxu4(bw[2], bw[3]));
        m4 = __vmaxu4(m4, m4 >> 16);
        m4 = __vmaxu4(m4, m4 >> 8);
        if (a2 >= (int)(m4 & 0xFFu)) break;
        ulonglong2 up = bp[-(ady * 32)];
        ulonglong2 dn = bp[  ady * 32 ];
        unsigned a2b = a2 * 0x01010101u;   // per-byte add, sums < 256: no carry
        bw[0] = __vminu4(bw[0], __vminu4((unsigned)up.x,         (unsigned)dn.x)         + a2b);
        bw[1] = __vminu4(bw[1], __vminu4((unsigned)(up.x >> 32), (unsigned)(dn.x >> 32)) + a2b);
        bw[2] = __vminu4(bw[2], __vminu4((unsigned)up.y,         (unsigned)dn.y)         + a2b);
        bw[3] = __vminu4(bw[3], __vminu4((unsigned)(up.y >> 32), (unsigned)(dn.y >> 32)) + a2b);
    }

    __syncthreads();   // sTab ready

    // ---- pointwise math + 6 sums over 16 px ----
    // byte==0 <=> fg. |x| <= ~6 so exp(-x) never overflows:
    //   e = exp(-x); p = 1/(1+e); sp_neg = -log(p); sp_pos = x + sp_neg.
    // Per pixel only ONE sp is consumed: spv = sp_neg + (fg ? 0 : x).
    // sAll = Sfg + Sbg; Sbg derived in finalize.
    float s2 = (float)(__popc(__vseteq4(bw[0], 0u)) + __popc(__vseteq4(bw[1], 0u))
                     + __popc(__vseteq4(bw[2], 0u)) + __popc(__vseteq4(bw[3], 0u)));
    float s0 = 0.f, s1 = 0.f, s4 = 0.f, s5 = 0.f, sAll = 0.f;
    #pragma unroll
    for (int j = 0; j < 16; ++j) {
        float x_ = ((const float*)xv)[j];
        unsigned b2 = (bw[j >> 2] >> ((j & 3) * 8)) & 0xFFu;
        bool fg = (b2 == 0);

        float e      = __expf(-x_);
        float p      = __frcp_rn(1.0f + e);       // sigmoid(x)
        float sp_neg = -__logf(p);                // softplus(-x) = -log(p)
        float spv    = sp_neg + (fg ? 0.0f : x_); // sp_neg (fg) or sp_pos (bg)

        s1 += p;
        s4 = fmaf(sTab[b2], p, s4);
        sAll += spv;
        if (fg) {
            s0 += p;
            s5 += sp_neg;
        }
    }

    // ---- block reduction: warp shuffle -> shared -> per-sample atomics ----
    float vals[6] = {s0, s1, s2, s4, s5, sAll};
    __shared__ float shr[8 * 6];
    int lane = threadIdx.x & 31;
    int wid  = threadIdx.x >> 5;
    #pragma unroll
    for (int qq = 0; qq < 6; ++qq) {
        float v = vals[qq];
        #pragma unroll
        for (int o = 16; o; o >>= 1) v += __shfl_down_sync(0xffffffffu, v, o);
        if (lane == 0) shr[wid * 6 + qq] = v;
    }
    __syncthreads();
    if (threadIdx.x < 6) {
        float ssum = 0.0f;
        #pragma unroll
        for (int w = 0; w < 8; ++w) ssum += shr[w * 6 + threadIdx.x];
        atomicAdd(&g_acc[b * 8 + threadIdx.x], ssum);
    }

    // ---- last block finalizes ----
    __shared__ unsigned sIsLast;
    __threadfence();
    __syncthreads();
    if (threadIdx.x == 0)
        sIsLast = (atomicAdd(&g_done, 1u) == MAIN_GRID - 1) ? 1u : 0u;
    __syncthreads();
    if (sIsLast) {
        __shared__ float shp[64];
        if (threadIdx.x < 64) {
            int bb = threadIdx.x;
            const float Nf   = (float)NPIX;
            const float invN = 1.0f / Nf;
            float* a = &g_acc[bb * 8];
            float Sint = a[0], Spc = a[1], St = a[2];
            float Sbd  = a[3], Sfg = a[4], Sall = a[5];
            float Sbg  = Sall - Sfg;
            float Sbce = Sall;

            float dice = 1.0f - (2.0f * Sint + 1e-5f) / (Spc + St + 1e-5f);
            float base = dice + Sbce * invN;
            float boundary = Sbd * invN;
            float fgw = fminf(fmaxf((Nf - St) / (St + 1e-7f), 1.0f), 10.0f);
            float fgl = (St == 0.0f) ? 0.0f : (fgw * Sfg + Sbg) * invN;

            const float DW[3] = {2.0f, 3.0f, 5.0f};
            const float FW[3] = {1.0f, 1.5f, 3.0f};
            int ti = task_ids[bb];
            shp[bb] = base + DW[ti] * boundary + FW[ti] * fgl;  // BASE_W == 1
        }
        __syncthreads();
        if (threadIdx.x == 0) {
            float ssum = 0.0f;
            #pragma unroll
            for (int i = 0; i < 64; ++i) ssum += shp[i];
            out[0] = ssum * (1.0f / 64.0f);
        }
    }
}

// ---------------------------------------------------------------------------
extern "C" void kernel_launch(void* const* d_in, const int* in_sizes, int n_in,
                              void* d_out, int out_size)
{
    const float* preds = (const float*)d_in[0];
    const float* targs = (const float*)d_in[1];
    const int*   tids  = (const int*)d_in[2];
    float*       out   = (float*)d_out;

    dim3 mg(65, BN);   // 64 row-strips + 1 pad/init column
    maskdxh_kernel<<<mg, 512>>>((const float4*)targs);
    main_kernel<<<MAIN_GRID, 256>>>((const float4*)preds, tids, out);
}

// round 14
// speedup vs baseline: 1.0610x; 1.0610x over previous
#include <cuda_runtime.h>
#include <cuda_bf16.h>

// MultiTaskLoss: B=64 samples, 512x512, scalar loss output.
// R14: R13 with the reciprocal fixed (rcp.approx.f32, one MUFU op — R13's
//      __frcp_rn was a slow IEEE Newton sequence). Both MUFUs (RCP, LG2)
//      consume the same w = 1+exp(-x). Preds loads sunk below the DT loop.

#define BN 64
#define HH 512
#define WW 512
#define NPIX (HH * WW)
#define MAIN_GRID (BN * NPIX / 16 / 256)
#define PROWS (HH + 20)      // 10 pad rows top/bottom

__device__ unsigned long long g_dxh[BN * PROWS * WW / 8];   // horiz d^2, u8x8
__device__ float              g_acc[BN * 8];
__device__ unsigned           g_done;

// ---------------------------------------------------------------------------
__device__ __forceinline__ float frcp_approx(float w) {
    float r;
    asm("rcp.approx.f32 %0, %1;" : "=f"(r) : "f"(w));
    return r;
}

// nearest-set-bit distance^2 (clamped 101) from center (bit 10) of 21-bit window
__device__ __forceinline__ int win_d2(unsigned win) {
    unsigned lo = win & 0x7FFu;            // bits 0..10 (left side, center incl)
    unsigned hi = win >> 10;               // bits 0..10 (right side, center incl)
    int dl = __clz(lo) - 21;               // lo==0 -> 11 (no guard needed)
    int dh = __clz(__brev(hi));            // lowest set bit idx; hi==0 -> 32
    int d  = min(min(dl, dh), 11);
    return min(d * d, 101);
}

// ---------------------------------------------------------------------------
// Fused: build 8 row-masks in smem via ballots, then emit horizontal d^2 (u8).
// grid (65, 64): blockIdx.x==64 handles pad rows + accumulator init.
__global__ void __launch_bounds__(512) maskdxh_kernel(const float4* __restrict__ targets4) {
    int b = blockIdx.y;
    int t = threadIdx.x;

    if (blockIdx.x == 64) {
        for (int i = t; i < 20 * 64; i += 512) {
            int r = i >> 6;
            int row = (r < 10) ? r : r + 512;   // 0..9 and 522..531
            g_dxh[(b * PROWS + row) * 64 + (i & 63)] = 0x6565656565656565ull;
        }
        if (b == 0) {
            if (t < BN * 8) g_acc[t] = 0.0f;
            if (t == 0)     g_done = 0u;
        }
        return;
    }

    __shared__ unsigned smask[8][18];   // 8 rows, 16 words + 1 pad each side

    int y0 = blockIdx.x * 8;            // first of 8 rows this block owns

    if (t < 144) ((unsigned*)smask)[t] = 0u;
    __syncthreads();

    // --- build masks: 8 px/thread, 4-lane REDUX.OR -> one word / 32 px ---
    int g4 = ((b * NPIX + y0 * WW) >> 2) + t * 2;   // float4 index
    float4 v0 = targets4[g4 + 0];
    float4 v1 = targets4[g4 + 1];
    unsigned m =
          (v0.x > 0.5f ? 0x01u : 0u) | (v0.y > 0.5f ? 0x02u : 0u)
        | (v0.z > 0.5f ? 0x04u : 0u) | (v0.w > 0.5f ? 0x08u : 0u)
        | (v1.x > 0.5f ? 0x10u : 0u) | (v1.y > 0.5f ? 0x20u : 0u)
        | (v1.z > 0.5f ? 0x40u : 0u) | (v1.w > 0.5f ? 0x80u : 0u);

    unsigned lane  = t & 31;
    unsigned gmask = 0xFu << (lane & ~3u);          // 4-lane group = 32 px
    unsigned word  = __reduce_or_sync(gmask, m << ((lane & 3) * 8));
    if ((lane & 3) == 0) {
        int p0 = t * 8;
        smask[p0 >> 9][1 + ((p0 & 511) >> 5)] = word;
    }
    __syncthreads();

    // --- horizontal d^2, 8 px/thread (one u64 output) ---
    int r  = t >> 6;                    // row within strip
    int x0 = (t & 63) << 3;             // first pixel in row
    int s  = x0 - 10;
    const unsigned* rp = &smask[r][0] + 1 + (s >> 5);
    unsigned long long w =
        (((unsigned long long)rp[1] << 32) | rp[0]) >> (s & 31);
    unsigned long long out = 0ull;
    #pragma unroll
    for (int j = 0; j < 8; ++j) {
        unsigned win = (unsigned)(w >> j) & 0x1FFFFFu;
        out |= (unsigned long long)win_d2(win) << (8 * j);
    }
    g_dxh[(unsigned long long)(b * PROWS + 10 + y0 + r) * 64 + (x0 >> 3)] = out;
}

// ---------------------------------------------------------------------------
__global__ void __launch_bounds__(256, 6) main_kernel(
    const float4* __restrict__ preds4,
    const int*    __restrict__ task_ids,
    float*        __restrict__ out)
{
    __shared__ float sTab[102];
    if (threadIdx.x < 102) sTab[threadIdx.x] = fminf(sqrtf((float)threadIdx.x), 10.0f);

    int q = blockIdx.x * blockDim.x + threadIdx.x;   // 16-px strip index
    int b  = q >> 14;                                // 16384 strips per sample
    int y  = (q >> 5) & 511;
    int xo = q & 31;                                 // 16-px group in row

    // ---- byte-SIMD vertical DT (128-bit loads) ----
    const ulonglong2* bp = (const ulonglong2*)g_dxh + (b * PROWS + 10 + y) * 32 + xo;
    ulonglong2 cur = *bp;
    unsigned bw[4] = {(unsigned)cur.x, (unsigned)(cur.x >> 32),
                      (unsigned)cur.y, (unsigned)(cur.y >> 32)};

    #pragma unroll 1
    for (int ady = 1; ady <= 10; ++ady) {
        int a2 = ady * ady;
        unsigned m4 = __vmaxu4(__vmaxu4(bw[0], bw[1]), __vmaxu4(bw[2], bw[3]));
        m4 = __vmaxu4(m4, m4 >> 16);
        m4 = __vmaxu4(m4, m4 >> 8);
        if (a2 >= (int)(m4 & 0xFFu)) break;
        ulonglong2 up = bp[-(ady * 32)];
        ulonglong2 dn = bp[  ady * 32 ];
        unsigned a2b = a2 * 0x01010101u;   // per-byte add, sums < 256: no carry
        bw[0] = __vminu4(bw[0], __vminu4((unsigned)up.x,         (unsigned)dn.x)         + a2b);
        bw[1] = __vminu4(bw[1], __vminu4((unsigned)(up.x >> 32), (unsigned)(dn.x >> 32)) + a2b);
        bw[2] = __vminu4(bw[2], __vminu4((unsigned)up.y,         (unsigned)dn.y)         + a2b);
        bw[3] = __vminu4(bw[3], __vminu4((unsigned)(up.y >> 32), (unsigned)(dn.y >> 32)) + a2b);
    }

    // preds loads AFTER the DT loop (shorter live range, lower reg pressure)
    float4 xv[4];
    #pragma unroll
    for (int k = 0; k < 4; ++k) xv[k] = preds4[q * 4 + k];

    __syncthreads();   // sTab ready

    // ---- pointwise math + 6 sums over 16 px ----
    // byte==0 <=> fg. |x| <= ~6 so exp(-x) never overflows:
    //   w = 1+exp(-x); p = rcp.approx(w); sp_neg = log(w) = -log(p);
    //   sp_pos = x + sp_neg. One sp consumed per pixel; Sbg = Sall-Sfg.
    float s2 = (float)(__popc(__vseteq4(bw[0], 0u)) + __popc(__vseteq4(bw[1], 0u))
                     + __popc(__vseteq4(bw[2], 0u)) + __popc(__vseteq4(bw[3], 0u)));
    float s0 = 0.f, s1 = 0.f, s4 = 0.f, s5 = 0.f, sAll = 0.f;
    #pragma unroll
    for (int j = 0; j < 16; ++j) {
        float x_ = ((const float*)xv)[j];
        unsigned b2 = (bw[j >> 2] >> ((j & 3) * 8)) & 0xFFu;
        bool fg = (b2 == 0);

        float e      = __expf(-x_);
        float w      = 1.0f + e;
        float p      = frcp_approx(w);            // sigmoid(x)
        float sp_neg = __logf(w);                 // softplus(-x) = -log(p)
        float spv    = sp_neg + (fg ? 0.0f : x_); // sp_neg (fg) or sp_pos (bg)

        s1 += p;
        s4 = fmaf(sTab[b2], p, s4);
        sAll += spv;
        if (fg) {
            s0 += p;
            s5 += sp_neg;
        }
    }

    // ---- block reduction: warp shuffle -> shared -> per-sample atomics ----
    float vals[6] = {s0, s1, s2, s4, s5, sAll};
    __shared__ float shr[8 * 6];
    int lane = threadIdx.x & 31;
    int wid  = threadIdx.x >> 5;
    #pragma unroll
    for (int qq = 0; qq < 6; ++qq) {
        float v = vals[qq];
        #pragma unroll
        for (int o = 16; o; o >>= 1) v += __shfl_down_sync(0xffffffffu, v, o);
        if (lane == 0) shr[wid * 6 + qq] = v;
    }
    __syncthreads();
    if (threadIdx.x < 6) {
        float ssum = 0.0f;
        #pragma unroll
        for (int w = 0; w < 8; ++w) ssum += shr[w * 6 + threadIdx.x];
        atomicAdd(&g_acc[b * 8 + threadIdx.x], ssum);
    }

    // ---- last block finalizes ----
    __shared__ unsigned sIsLast;
    __threadfence();
    __syncthreads();
    if (threadIdx.x == 0)
        sIsLast = (atomicAdd(&g_done, 1u) == MAIN_GRID - 1) ? 1u : 0u;
    __syncthreads();
    if (sIsLast) {
        __shared__ float shp[64];
        if (threadIdx.x < 64) {
            int bb = threadIdx.x;
            const float Nf   = (float)NPIX;
            const float invN = 1.0f / Nf;
            float* a = &g_acc[bb * 8];
            float Sint = a[0], Spc = a[1], St = a[2];
            float Sbd  = a[3], Sfg = a[4], Sall = a[5];
            float Sbg  = Sall - Sfg;
            float Sbce = Sall;

            float dice = 1.0f - (2.0f * Sint + 1e-5f) / (Spc + St + 1e-5f);
            float base = dice + Sbce * invN;
            float boundary = Sbd * invN;
            float fgw = fminf(fmaxf((Nf - St) / (St + 1e-7f), 1.0f), 10.0f);
            float fgl = (St == 0.0f) ? 0.0f : (fgw * Sfg + Sbg) * invN;

            const float DW[3] = {2.0f, 3.0f, 5.0f};
            const float FW[3] = {1.0f, 1.5f, 3.0f};
            int ti = task_ids[bb];
            shp[bb] = base + DW[ti] * boundary + FW[ti] * fgl;  // BASE_W == 1
        }
        __syncthreads();
        if (threadIdx.x == 0) {
            float ssum = 0.0f;
            #pragma unroll
            for (int i = 0; i < 64; ++i) ssum += shp[i];
            out[0] = ssum * (1.0f / 64.0f);
        }
    }
}

// ---------------------------------------------------------------------------
extern "C" void kernel_launch(void* const* d_in, const int* in_sizes, int n_in,
                              void* d_out, int out_size)
{
    const float* preds = (const float*)d_in[0];
    const float* targs = (const float*)d_in[1];
    const int*   tids  = (const int*)d_in[2];
    float*       out   = (float*)d_out;

    dim3 mg(65, BN);   // 64 row-strips + 1 pad/init column
    maskdxh_kernel<<<mg, 512>>>((const float4*)targs);
    main_kernel<<<MAIN_GRID, 256>>>((const float4*)preds, tids, out);
}